// round 6
// baseline (speedup 1.0000x reference)
#include <cuda_runtime.h>

typedef unsigned long long u64;
#define N_NODES 50000
#define N_EDGES 800000
#define DIM 128
#define KPI 0.62831853071795865f
#define FULL 0xffffffffu

// ---- f32x2 helpers: natural register-pair usage only ----
__device__ __forceinline__ u64 pkf(float x, float y) {
    u64 r; asm("mov.b64 %0,{%1,%2};" : "=l"(r) : "f"(x), "f"(y)); return r;
}
__device__ __forceinline__ void upkf(u64 v, float& x, float& y) {
    asm("mov.b64 {%0,%1},%2;" : "=f"(x), "=f"(y) : "l"(v));
}
__device__ __forceinline__ u64 fma2(u64 a, u64 b, u64 c) {
    u64 d; asm("fma.rn.f32x2 %0,%1,%2,%3;" : "=l"(d) : "l"(a), "l"(b), "l"(c)); return d;
}
__device__ __forceinline__ u64 mul2(u64 a, u64 b) {
    u64 d; asm("mul.rn.f32x2 %0,%1,%2;" : "=l"(d) : "l"(a), "l"(b)); return d;
}
__device__ __forceinline__ float hadd2(u64 v) {
    float x, y; upkf(v, x, y); return x + y;
}

// ---- scratch ----
__device__ float g_P[(size_t)N_NODES * 1024];   // [n][h][128], pre-scaled by 0.25
__device__ float g_c[N_NODES * 8];              // (q.b_K)*0.25
__device__ float g_WKT[DIM * DIM];
__device__ int   g_counts[N_NODES];
__device__ int   g_offsets[N_NODES + 1];
__device__ int   g_cursor[N_NODES];
__device__ int2  g_pe[N_EDGES];                 // (edge, phi bits) CSR order

// ---- CSR build ----
__global__ void k_zero() {
    int i = blockIdx.x * blockDim.x + threadIdx.x;
    if (i < N_NODES) g_counts[i] = 0;
}
__global__ void k_hist(const int* __restrict__ ei) {
    int e = blockIdx.x * blockDim.x + threadIdx.x;
    if (e < N_EDGES) atomicAdd(&g_counts[ei[N_EDGES + e]], 1);
}
__global__ void k_scan() {
    __shared__ int wsum[32];
    int t = threadIdx.x, lane = t & 31, wid = t >> 5;
    int carry = 0;
    for (int base = 0; base < N_NODES; base += 1024) {
        int i = base + t;
        int v = (i < N_NODES) ? g_counts[i] : 0;
        int x = v;
        #pragma unroll
        for (int o = 1; o < 32; o <<= 1) { int y = __shfl_up_sync(FULL, x, o); if (lane >= o) x += y; }
        if (lane == 31) wsum[wid] = x;
        __syncthreads();
        if (wid == 0) {
            int s = wsum[lane];
            #pragma unroll
            for (int o = 1; o < 32; o <<= 1) { int y = __shfl_up_sync(FULL, s, o); if (lane >= o) s += y; }
            wsum[lane] = s;
        }
        __syncthreads();
        int excl = x - v + (wid ? wsum[wid - 1] : 0);
        if (i < N_NODES) { g_offsets[i] = carry + excl; g_cursor[i] = carry + excl; }
        carry += wsum[31];
        __syncthreads();
    }
    if (t == 0) g_offsets[N_NODES] = carry;
}
__global__ void k_scatter(const int* __restrict__ ei, const float* __restrict__ elen) {
    int e = blockIdx.x * blockDim.x + threadIdx.x;
    if (e < N_EDGES) {
        int j = ei[N_EDGES + e];
        int pos = atomicAdd(&g_cursor[j], 1);
        float phi = fmaf(0.5f, __cosf(elen[e] * KPI), 0.5f);
        g_pe[pos] = make_int2(e, __float_as_int(phi));
    }
}
__global__ void k_wkt(const float* __restrict__ WK) {
    int i = blockIdx.x * blockDim.x + threadIdx.x;
    if (i < DIM * DIM) g_WKT[(i % DIM) * DIM + (i / DIM)] = WK[i];
}

// ---- node precompute, 4 nodes/block, f32x2 over node pairs ----
__global__ void __launch_bounds__(128) k_qp(
    const float* __restrict__ x, const float* __restrict__ WQ,
    const float* __restrict__ bQ, const float* __restrict__ bK)
{
    __shared__ u64 sx01[DIM], sx23[DIM], sq01[DIM], sq23[DIM];
    int nb = blockIdx.x * 4, t = threadIdx.x;
    {
        float x0 = x[(size_t)(nb + 0) * DIM + t];
        float x1 = x[(size_t)(nb + 1) * DIM + t];
        float x2 = x[(size_t)(nb + 2) * DIM + t];
        float x3 = x[(size_t)(nb + 3) * DIM + t];
        sx01[t] = pkf(x0, x1); sx23[t] = pkf(x2, x3);
    }
    __syncthreads();
    float bq = bQ[t];
    u64 q01 = pkf(bq, bq), q23 = q01;
    #pragma unroll 4
    for (int s = 0; s < DIM; s++) {
        float w = WQ[s * DIM + t];
        u64 w2 = pkf(w, w);
        q01 = fma2(sx01[s], w2, q01);
        q23 = fma2(sx23[s], w2, q23);
    }
    sq01[t] = q01; sq23[t] = q23;
    __syncthreads();
    #pragma unroll 2
    for (int h = 0; h < 8; h++) {
        u64 p01 = 0ull, p23 = 0ull;
        #pragma unroll
        for (int k = 0; k < 16; k++) {
            float w = g_WKT[(h * 16 + k) * DIM + t];
            u64 w2 = pkf(w, w);
            p01 = fma2(sq01[h * 16 + k], w2, p01);
            p23 = fma2(sq23[h * 16 + k], w2, p23);
        }
        float a, b, c, d;
        upkf(p01, a, b); upkf(p23, c, d);
        g_P[(size_t)(nb + 0) * 1024 + h * DIM + t] = 0.25f * a;
        g_P[(size_t)(nb + 1) * 1024 + h * DIM + t] = 0.25f * b;
        g_P[(size_t)(nb + 2) * 1024 + h * DIM + t] = 0.25f * c;
        g_P[(size_t)(nb + 3) * 1024 + h * DIM + t] = 0.25f * d;
    }
    if (t < 32) {
        int i = t >> 3, h = t & 7;
        float cc = 0.f;
        #pragma unroll
        for (int k = 0; k < 16; k++) {
            float qa, qb;
            upkf((i < 2) ? sq01[h * 16 + k] : sq23[h * 16 + k], qa, qb);
            cc = fmaf((i & 1) ? qb : qa, bK[h * 16 + k], cc);
        }
        g_c[(nb + i) * 8 + h] = 0.25f * cc;
    }
}

// ---- fused edge pass (warp=node) + block-cooperative epilogue ----
__global__ void __launch_bounds__(256, 2) k_edge(
    const float4* __restrict__ ea4,
    const float* __restrict__ WV, const float* __restrict__ bV,
    const float* __restrict__ WO, const float* __restrict__ bO,
    float* __restrict__ out)
{
    __shared__ float sU[8][8][DIM];   // [node][head][dim], normalized
    __shared__ float sT[8][8];        // [node][head] = sum(alpha*phi)
    __shared__ u64   snoP[4][DIM];    // node_out as node-pairs (n even, n odd)
    int tid = threadIdx.x, w = tid >> 5, l = tid & 31;
    int n = blockIdx.x * 8 + w;

    // P: lane l holds dims 4l..4l+3 of all 8 heads as 2 natural u64 pairs each
    u64 P2[8][2];
    #pragma unroll
    for (int h = 0; h < 8; h++) {
        float4 v = reinterpret_cast<const float4*>(g_P + (size_t)n * 1024 + h * DIM)[l];
        P2[h][0] = pkf(v.x, v.y);
        P2[h][1] = pkf(v.z, v.w);
    }
    float ch = g_c[n * 8 + (l >> 2)];

    u64 U2[8][2];
    #pragma unroll
    for (int h = 0; h < 8; h++) { U2[h][0] = 0ull; U2[h][1] = 0ull; }
    float ssum = 0.f, tsum = 0.f;
    bool b4 = (l & 16), b3 = (l & 8), b2 = (l & 4);

    int beg = g_offsets[n], end = g_offsets[n + 1];
    int2 pe0 = make_int2(0, 0), pe1 = pe0;
    float4 a0 = make_float4(0.f, 0.f, 0.f, 0.f), a1 = a0;
    if (beg < end)     { pe0 = g_pe[beg];     a0 = ea4[(size_t)pe0.x * 32 + l]; }
    if (beg + 1 < end) { pe1 = g_pe[beg + 1]; a1 = ea4[(size_t)pe1.x * 32 + l]; }

    for (int i = beg; i < end; i++) {
        float4 ac = a0; float phi = __int_as_float(pe0.y);
        pe0 = pe1; a0 = a1;
        if (i + 2 < end) { pe1 = g_pe[i + 2]; a1 = ea4[(size_t)pe1.x * 32 + l]; }

        u64 axy = pkf(ac.x, ac.y), azw = pkf(ac.z, ac.w);

        // partial dots per head over this lane's 4 dims (2 FFMA2 + 1 hadd each)
        float p[8];
        #pragma unroll
        for (int h = 0; h < 8; h++)
            p[h] = hadd2(fma2(axy, P2[h][0], mul2(azw, P2[h][1])));

        // scalar head-halving butterfly: lane ends with full score of head (l>>2)
        float r0, r1, r2, r3;
        {
            float t0 = b4 ? p[0] : p[4], t1 = b4 ? p[1] : p[5];
            float t2 = b4 ? p[2] : p[6], t3 = b4 ? p[3] : p[7];
            r0 = (b4 ? p[4] : p[0]) + __shfl_xor_sync(FULL, t0, 16);
            r1 = (b4 ? p[5] : p[1]) + __shfl_xor_sync(FULL, t1, 16);
            r2 = (b4 ? p[6] : p[2]) + __shfl_xor_sync(FULL, t2, 16);
            r3 = (b4 ? p[7] : p[3]) + __shfl_xor_sync(FULL, t3, 16);
        }
        float s0, s1;
        {
            float t0 = b3 ? r0 : r2, t1 = b3 ? r1 : r3;
            s0 = (b3 ? r2 : r0) + __shfl_xor_sync(FULL, t0, 8);
            s1 = (b3 ? r3 : r1) + __shfl_xor_sync(FULL, t1, 8);
        }
        float s;
        {
            float t0 = b2 ? s0 : s1;
            s = (b2 ? s1 : s0) + __shfl_xor_sync(FULL, t0, 4);
        }
        s += __shfl_xor_sync(FULL, s, 2);
        s += __shfl_xor_sync(FULL, s, 1);

        float ex = __expf(s + ch);   // P, ch pre-scaled by 1/sqrt(d_k)
        float wh = ex * phi;
        ssum += ex; tsum += wh;

        // broadcast per-head weight, accumulate U as dim-pairs (2 FFMA2/head)
        #pragma unroll
        for (int h = 0; h < 8; h++) {
            float whh = __shfl_sync(FULL, wh, 4 * h);
            u64 w2 = pkf(whh, whh);
            U2[h][0] = fma2(w2, axy, U2[h][0]);
            U2[h][1] = fma2(w2, azw, U2[h][1]);
        }
    }

    // normalize + stage (lane's ssum is for head l>>2)
    float invm = (ssum > 0.f) ? (1.f / ssum) : 0.f;
    if ((l & 3) == 0) sT[w][l >> 2] = tsum * invm;
    #pragma unroll
    for (int h = 0; h < 8; h++) {
        float ivh = __shfl_sync(FULL, invm, 4 * h);
        u64 iv2 = pkf(ivh, ivh);
        float va, vb, vc, vd;
        upkf(mul2(U2[h][0], iv2), va, vb);
        upkf(mul2(U2[h][1], iv2), vc, vd);
        reinterpret_cast<float4*>(&sU[w][h][0])[l] = make_float4(va, vb, vc, vd);
    }
    __syncthreads();

    // GEMM1 (scalar, 4 nodes/thread): node_out = Unorm @ W_V + sT*b_V
    int c = tid & 127, g = tid >> 7, h = c >> 4;
    int n0 = 4 * g, n1 = n0 + 1, n2 = n0 + 2, n3 = n0 + 3;
    {
        float bv = bV[c];
        float a0c = sT[n0][h] * bv, a1c = sT[n1][h] * bv;
        float a2c = sT[n2][h] * bv, a3c = sT[n3][h] * bv;
        const float4* u0 = reinterpret_cast<const float4*>(&sU[n0][h][0]);
        const float4* u1 = reinterpret_cast<const float4*>(&sU[n1][h][0]);
        const float4* u2 = reinterpret_cast<const float4*>(&sU[n2][h][0]);
        const float4* u3 = reinterpret_cast<const float4*>(&sU[n3][h][0]);
        #pragma unroll 8
        for (int d4 = 0; d4 < 32; d4++) {
            float w0 = WV[(4 * d4 + 0) * DIM + c];
            float w1 = WV[(4 * d4 + 1) * DIM + c];
            float w2 = WV[(4 * d4 + 2) * DIM + c];
            float w3 = WV[(4 * d4 + 3) * DIM + c];
            float4 v;
            v = u0[d4]; a0c = fmaf(v.x, w0, fmaf(v.y, w1, fmaf(v.z, w2, fmaf(v.w, w3, a0c))));
            v = u1[d4]; a1c = fmaf(v.x, w0, fmaf(v.y, w1, fmaf(v.z, w2, fmaf(v.w, w3, a1c))));
            v = u2[d4]; a2c = fmaf(v.x, w0, fmaf(v.y, w1, fmaf(v.z, w2, fmaf(v.w, w3, a2c))));
            v = u3[d4]; a3c = fmaf(v.x, w0, fmaf(v.y, w1, fmaf(v.z, w2, fmaf(v.w, w3, a3c))));
        }
        snoP[2 * g][c]     = pkf(a0c, a1c);  // (node n0, n1) pair
        snoP[2 * g + 1][c] = pkf(a2c, a3c);  // (node n2, n3) pair
    }
    __syncthreads();

    // GEMM2 (f32x2 over node pairs): out = node_out @ W_O + b_O
    {
        float bo = bO[c];
        u64 o01 = pkf(bo, bo), o23 = o01;
        const u64* v01 = &snoP[2 * g][0];
        const u64* v23 = &snoP[2 * g + 1][0];
        #pragma unroll 8
        for (int d = 0; d < DIM; d++) {
            float wv = WO[d * DIM + c];
            u64 w2 = pkf(wv, wv);
            o01 = fma2(v01[d], w2, o01);
            o23 = fma2(v23[d], w2, o23);
        }
        size_t base = (size_t)blockIdx.x * 8;
        float y0, y1, y2, y3;
        upkf(o01, y0, y1); upkf(o23, y2, y3);
        out[(base + n0) * DIM + c] = y0;
        out[(base + n1) * DIM + c] = y1;
        out[(base + n2) * DIM + c] = y2;
        out[(base + n3) * DIM + c] = y3;
    }
}

extern "C" void kernel_launch(void* const* d_in, const int* in_sizes, int n_in,
                              void* d_out, int out_size) {
    const float* x    = (const float*)d_in[0];
    const int*   ei   = (const int*)  d_in[1];
    const float* ea   = (const float*)d_in[2];
    const float* elen = (const float*)d_in[3];
    const float* WQ   = (const float*)d_in[4];
    const float* bQ   = (const float*)d_in[5];
    const float* WK   = (const float*)d_in[6];
    const float* bK   = (const float*)d_in[7];
    const float* WV   = (const float*)d_in[8];
    const float* bV   = (const float*)d_in[9];
    const float* WO   = (const float*)d_in[10];
    const float* bO   = (const float*)d_in[11];
    float* out = (float*)d_out;

    k_zero<<<(N_NODES + 255) / 256, 256>>>();
    k_hist<<<(N_EDGES + 255) / 256, 256>>>(ei);
    k_scan<<<1, 1024>>>();
    k_scatter<<<(N_EDGES + 255) / 256, 256>>>(ei, elen);
    k_wkt<<<(DIM * DIM + 255) / 256, 256>>>(WK);
    k_qp<<<N_NODES / 4, 128>>>(x, WQ, bQ, bK);
    k_edge<<<N_NODES / 8, 256>>>((const float4*)ea, WV, bV, WO, bO, out);
}

// round 7
// speedup vs baseline: 1.0450x; 1.0450x over previous
#include <cuda_runtime.h>

#define N_NODES 50000
#define N_EDGES 800000
#define DIM 128
#define KPI 0.62831853071795865f
#define FULL 0xffffffffu

// ---- scratch ----
__device__ float g_P[(size_t)N_NODES * 1024];   // [n][h][128], pre-scaled by 0.25
__device__ float g_c[N_NODES * 8];              // (q.b_K)*0.25
__device__ float g_WKT[DIM * DIM];
__device__ int   g_counts[N_NODES];
__device__ int   g_offsets[N_NODES + 1];
__device__ int   g_cursor[N_NODES];
__device__ int2  g_pe[N_EDGES];                 // (edge, phi bits) CSR order
__device__ int   g_dhist[64];
__device__ int   g_dcur[64];
__device__ int   g_nperm[N_NODES];              // nodes sorted by degree (desc)

// ---- CSR build ----
__global__ void k_zero() {
    int i = blockIdx.x * blockDim.x + threadIdx.x;
    if (i < N_NODES) g_counts[i] = 0;
    if (i < 64) g_dhist[i] = 0;
}
__global__ void k_hist(const int* __restrict__ ei) {
    int e = blockIdx.x * blockDim.x + threadIdx.x;
    if (e < N_EDGES) atomicAdd(&g_counts[ei[N_EDGES + e]], 1);
}
__global__ void k_scan() {
    __shared__ int wsum[32];
    int t = threadIdx.x, lane = t & 31, wid = t >> 5;
    int carry = 0;
    for (int base = 0; base < N_NODES; base += 1024) {
        int i = base + t;
        int v = (i < N_NODES) ? g_counts[i] : 0;
        int x = v;
        #pragma unroll
        for (int o = 1; o < 32; o <<= 1) { int y = __shfl_up_sync(FULL, x, o); if (lane >= o) x += y; }
        if (lane == 31) wsum[wid] = x;
        __syncthreads();
        if (wid == 0) {
            int s = wsum[lane];
            #pragma unroll
            for (int o = 1; o < 32; o <<= 1) { int y = __shfl_up_sync(FULL, s, o); if (lane >= o) s += y; }
            wsum[lane] = s;
        }
        __syncthreads();
        int excl = x - v + (wid ? wsum[wid - 1] : 0);
        if (i < N_NODES) { g_offsets[i] = carry + excl; g_cursor[i] = carry + excl; }
        carry += wsum[31];
        __syncthreads();
    }
    if (t == 0) g_offsets[N_NODES] = carry;
}
__global__ void k_scatter(const int* __restrict__ ei, const float* __restrict__ elen) {
    int e = blockIdx.x * blockDim.x + threadIdx.x;
    if (e < N_EDGES) {
        int j = ei[N_EDGES + e];
        int pos = atomicAdd(&g_cursor[j], 1);
        float phi = fmaf(0.5f, __cosf(elen[e] * KPI), 0.5f);
        g_pe[pos] = make_int2(e, __float_as_int(phi));
    }
}

// ---- degree counting-sort (descending) for balanced blocks ----
__global__ void k_dhist() {
    int i = blockIdx.x * blockDim.x + threadIdx.x;
    if (i < N_NODES) {
        int d = min(g_counts[i], 63);
        atomicAdd(&g_dhist[63 - d], 1);
    }
}
__global__ void k_dscan() {   // 64 threads
    __shared__ int ws[2];
    int t = threadIdx.x;
    int v = g_dhist[t], x = v;
    #pragma unroll
    for (int o = 1; o < 32; o <<= 1) { int y = __shfl_up_sync(FULL, x, o); if ((t & 31) >= o) x += y; }
    if ((t & 31) == 31) ws[t >> 5] = x;
    __syncthreads();
    int add = (t >= 32) ? ws[0] : 0;
    g_dcur[t] = x - v + add;
}
__global__ void k_dscatter() {
    int i = blockIdx.x * blockDim.x + threadIdx.x;
    if (i < N_NODES) {
        int d = min(g_counts[i], 63);
        int pos = atomicAdd(&g_dcur[63 - d], 1);
        g_nperm[pos] = i;
    }
}

__global__ void k_wkt(const float* __restrict__ WK) {
    int i = blockIdx.x * blockDim.x + threadIdx.x;
    if (i < DIM * DIM) g_WKT[(i % DIM) * DIM + (i / DIM)] = WK[i];
}

// ---- node precompute, 4 nodes/block: weights stream once per 4 nodes ----
__global__ void __launch_bounds__(128) k_qp(
    const float* __restrict__ x, const float* __restrict__ WQ,
    const float* __restrict__ bQ, const float* __restrict__ bK)
{
    __shared__ float sx[4][DIM], sq[4][DIM];
    int nb = blockIdx.x * 4, t = threadIdx.x;
    #pragma unroll
    for (int i = 0; i < 4; i++) sx[i][t] = x[(size_t)(nb + i) * DIM + t];
    __syncthreads();
    float q0 = bQ[t], q1 = q0, q2 = q0, q3 = q0;
    #pragma unroll 4
    for (int s = 0; s < DIM; s++) {
        float w = WQ[s * DIM + t];
        q0 = fmaf(sx[0][s], w, q0);
        q1 = fmaf(sx[1][s], w, q1);
        q2 = fmaf(sx[2][s], w, q2);
        q3 = fmaf(sx[3][s], w, q3);
    }
    sq[0][t] = q0; sq[1][t] = q1; sq[2][t] = q2; sq[3][t] = q3;
    __syncthreads();
    #pragma unroll
    for (int h = 0; h < 8; h++) {
        float p0 = 0.f, p1 = 0.f, p2 = 0.f, p3 = 0.f;
        #pragma unroll
        for (int k = 0; k < 16; k++) {
            float w = g_WKT[(h * 16 + k) * DIM + t];
            p0 = fmaf(sq[0][h * 16 + k], w, p0);
            p1 = fmaf(sq[1][h * 16 + k], w, p1);
            p2 = fmaf(sq[2][h * 16 + k], w, p2);
            p3 = fmaf(sq[3][h * 16 + k], w, p3);
        }
        g_P[(size_t)(nb + 0) * 1024 + h * DIM + t] = 0.25f * p0;
        g_P[(size_t)(nb + 1) * 1024 + h * DIM + t] = 0.25f * p1;
        g_P[(size_t)(nb + 2) * 1024 + h * DIM + t] = 0.25f * p2;
        g_P[(size_t)(nb + 3) * 1024 + h * DIM + t] = 0.25f * p3;
    }
    if (t < 32) {
        int i = t >> 3, h = t & 7;
        float cc = 0.f;
        #pragma unroll
        for (int k = 0; k < 16; k++) cc = fmaf(sq[i][h * 16 + k], bK[h * 16 + k], cc);
        g_c[(nb + i) * 8 + h] = cc * 0.25f;
    }
}

// ---- fused edge pass (warp=node, degree-balanced) + cooperative epilogue ----
__global__ void __launch_bounds__(256, 2) k_edge(
    const float4* __restrict__ ea4,
    const float* __restrict__ WV, const float* __restrict__ bV,
    const float* __restrict__ WO, const float* __restrict__ bO,
    float* __restrict__ out)
{
    __shared__ float sU[8][8][DIM];   // [node][head][dim], normalized
    __shared__ float sT[8][8];        // [node][head] = sum(alpha*phi)
    __shared__ float sno[8][DIM];     // node_out
    __shared__ int   sNid[8];         // global node ids for this block
    int tid = threadIdx.x, w = tid >> 5, l = tid & 31;
    int n = g_nperm[blockIdx.x * 8 + w];
    if (l == 0) sNid[w] = n;

    // P: lane l holds dims 4l..4l+3 of all 8 heads (pre-scaled 0.25)
    float4 P4[8];
    #pragma unroll
    for (int h = 0; h < 8; h++)
        P4[h] = reinterpret_cast<const float4*>(g_P + (size_t)n * 1024 + h * DIM)[l];
    float ch = g_c[n * 8 + (l >> 2)];

    float4 U[8];
    #pragma unroll
    for (int h = 0; h < 8; h++) U[h] = make_float4(0.f, 0.f, 0.f, 0.f);
    float ssum = 0.f, tsum = 0.f;
    bool b4 = (l & 16), b3 = (l & 8), b2 = (l & 4);

    int beg = g_offsets[n], end = g_offsets[n + 1];
    int2 pe0 = make_int2(0, 0), pe1 = pe0;
    float4 a0 = make_float4(0.f, 0.f, 0.f, 0.f), a1 = a0;
    if (beg < end)     { pe0 = g_pe[beg];     a0 = ea4[(size_t)pe0.x * 32 + l]; }
    if (beg + 1 < end) { pe1 = g_pe[beg + 1]; a1 = ea4[(size_t)pe1.x * 32 + l]; }

    for (int i = beg; i < end; i++) {
        float4 ac = a0; float phi = __int_as_float(pe0.y);
        pe0 = pe1; a0 = a1;
        if (i + 2 < end) { pe1 = g_pe[i + 2]; a1 = ea4[(size_t)pe1.x * 32 + l]; }

        // partial dots: p[h] over this lane's 4 dims
        float p[8];
        #pragma unroll
        for (int h = 0; h < 8; h++)
            p[h] = fmaf(ac.x, P4[h].x, fmaf(ac.y, P4[h].y, fmaf(ac.z, P4[h].z, ac.w * P4[h].w)));

        // head-halving butterfly: lane ends with full score of head (l>>2)
        float r0, r1, r2, r3;
        {
            float t0 = b4 ? p[0] : p[4], t1 = b4 ? p[1] : p[5];
            float t2 = b4 ? p[2] : p[6], t3 = b4 ? p[3] : p[7];
            r0 = (b4 ? p[4] : p[0]) + __shfl_xor_sync(FULL, t0, 16);
            r1 = (b4 ? p[5] : p[1]) + __shfl_xor_sync(FULL, t1, 16);
            r2 = (b4 ? p[6] : p[2]) + __shfl_xor_sync(FULL, t2, 16);
            r3 = (b4 ? p[7] : p[3]) + __shfl_xor_sync(FULL, t3, 16);
        }
        float s0, s1;
        {
            float t0 = b3 ? r0 : r2, t1 = b3 ? r1 : r3;
            s0 = (b3 ? r2 : r0) + __shfl_xor_sync(FULL, t0, 8);
            s1 = (b3 ? r3 : r1) + __shfl_xor_sync(FULL, t1, 8);
        }
        float s;
        {
            float t0 = b2 ? s0 : s1;
            s = (b2 ? s1 : s0) + __shfl_xor_sync(FULL, t0, 4);
        }
        s += __shfl_xor_sync(FULL, s, 2);
        s += __shfl_xor_sync(FULL, s, 1);

        float ex = __expf(s + ch);   // P, ch pre-scaled by 1/sqrt(d_k)
        float wh = ex * phi;
        ssum += ex; tsum += wh;

        // broadcast per-head weights, accumulate U
        #pragma unroll
        for (int h = 0; h < 8; h++) {
            float whh = __shfl_sync(FULL, wh, 4 * h);
            U[h].x = fmaf(whh, ac.x, U[h].x);
            U[h].y = fmaf(whh, ac.y, U[h].y);
            U[h].z = fmaf(whh, ac.z, U[h].z);
            U[h].w = fmaf(whh, ac.w, U[h].w);
        }
    }

    // normalize + stage (lane's ssum is for head l>>2)
    float invm = (ssum > 0.f) ? (1.f / ssum) : 0.f;
    if ((l & 3) == 0) sT[w][l >> 2] = tsum * invm;
    #pragma unroll
    for (int h = 0; h < 8; h++) {
        float ivh = __shfl_sync(FULL, invm, 4 * h);
        float4 v = make_float4(U[h].x * ivh, U[h].y * ivh, U[h].z * ivh, U[h].w * ivh);
        reinterpret_cast<float4*>(&sU[w][h][0])[l] = v;
    }
    __syncthreads();

    // GEMM1: node_out[n,c] = sum_d Unorm[n,h(c),d]*WV[d,c] + sT[n,h(c)]*bV[c]
    int c = tid & 127, g = tid >> 7, h = c >> 4;
    int n0 = 4 * g, n1 = n0 + 1, n2 = n0 + 2, n3 = n0 + 3;
    {
        float bv = bV[c];
        float a0c = sT[n0][h] * bv, a1c = sT[n1][h] * bv;
        float a2c = sT[n2][h] * bv, a3c = sT[n3][h] * bv;
        const float4* u0 = reinterpret_cast<const float4*>(&sU[n0][h][0]);
        const float4* u1 = reinterpret_cast<const float4*>(&sU[n1][h][0]);
        const float4* u2 = reinterpret_cast<const float4*>(&sU[n2][h][0]);
        const float4* u3 = reinterpret_cast<const float4*>(&sU[n3][h][0]);
        #pragma unroll 8
        for (int d4 = 0; d4 < 32; d4++) {
            float w0 = WV[(4 * d4 + 0) * DIM + c];
            float w1 = WV[(4 * d4 + 1) * DIM + c];
            float w2 = WV[(4 * d4 + 2) * DIM + c];
            float w3 = WV[(4 * d4 + 3) * DIM + c];
            float4 v;
            v = u0[d4]; a0c = fmaf(v.x, w0, fmaf(v.y, w1, fmaf(v.z, w2, fmaf(v.w, w3, a0c))));
            v = u1[d4]; a1c = fmaf(v.x, w0, fmaf(v.y, w1, fmaf(v.z, w2, fmaf(v.w, w3, a1c))));
            v = u2[d4]; a2c = fmaf(v.x, w0, fmaf(v.y, w1, fmaf(v.z, w2, fmaf(v.w, w3, a2c))));
            v = u3[d4]; a3c = fmaf(v.x, w0, fmaf(v.y, w1, fmaf(v.z, w2, fmaf(v.w, w3, a3c))));
        }
        sno[n0][c] = a0c; sno[n1][c] = a1c; sno[n2][c] = a2c; sno[n3][c] = a3c;
    }
    __syncthreads();

    // GEMM2: out[orig node] = node_out @ W_O + b_O
    {
        float bo = bO[c];
        float o0 = bo, o1 = bo, o2 = bo, o3 = bo;
        const float4* v0 = reinterpret_cast<const float4*>(&sno[n0][0]);
        const float4* v1 = reinterpret_cast<const float4*>(&sno[n1][0]);
        const float4* v2 = reinterpret_cast<const float4*>(&sno[n2][0]);
        const float4* v3 = reinterpret_cast<const float4*>(&sno[n3][0]);
        #pragma unroll 8
        for (int d4 = 0; d4 < 32; d4++) {
            float w0 = WO[(4 * d4 + 0) * DIM + c];
            float w1 = WO[(4 * d4 + 1) * DIM + c];
            float w2 = WO[(4 * d4 + 2) * DIM + c];
            float w3 = WO[(4 * d4 + 3) * DIM + c];
            float4 v;
            v = v0[d4]; o0 = fmaf(v.x, w0, fmaf(v.y, w1, fmaf(v.z, w2, fmaf(v.w, w3, o0))));
            v = v1[d4]; o1 = fmaf(v.x, w0, fmaf(v.y, w1, fmaf(v.z, w2, fmaf(v.w, w3, o1))));
            v = v2[d4]; o2 = fmaf(v.x, w0, fmaf(v.y, w1, fmaf(v.z, w2, fmaf(v.w, w3, o2))));
            v = v3[d4]; o3 = fmaf(v.x, w0, fmaf(v.y, w1, fmaf(v.z, w2, fmaf(v.w, w3, o3))));
        }
        out[(size_t)sNid[n0] * DIM + c] = o0;
        out[(size_t)sNid[n1] * DIM + c] = o1;
        out[(size_t)sNid[n2] * DIM + c] = o2;
        out[(size_t)sNid[n3] * DIM + c] = o3;
    }
}

extern "C" void kernel_launch(void* const* d_in, const int* in_sizes, int n_in,
                              void* d_out, int out_size) {
    const float* x    = (const float*)d_in[0];
    const int*   ei   = (const int*)  d_in[1];
    const float* ea   = (const float*)d_in[2];
    const float* elen = (const float*)d_in[3];
    const float* WQ   = (const float*)d_in[4];
    const float* bQ   = (const float*)d_in[5];
    const float* WK   = (const float*)d_in[6];
    const float* bK   = (const float*)d_in[7];
    const float* WV   = (const float*)d_in[8];
    const float* bV   = (const float*)d_in[9];
    const float* WO   = (const float*)d_in[10];
    const float* bO   = (const float*)d_in[11];
    float* out = (float*)d_out;

    k_zero<<<(N_NODES + 255) / 256, 256>>>();
    k_hist<<<(N_EDGES + 255) / 256, 256>>>(ei);
    k_scan<<<1, 1024>>>();
    k_scatter<<<(N_EDGES + 255) / 256, 256>>>(ei, elen);
    k_dhist<<<(N_NODES + 255) / 256, 256>>>();
    k_dscan<<<1, 64>>>();
    k_dscatter<<<(N_NODES + 255) / 256, 256>>>();
    k_wkt<<<(DIM * DIM + 255) / 256, 256>>>(WK);
    k_qp<<<N_NODES / 4, 128>>>(x, WQ, bQ, bK);
    k_edge<<<N_NODES / 8, 256>>>((const float4*)ea, WV, bV, WO, bO, out);
}

// round 8
// speedup vs baseline: 1.3055x; 1.2493x over previous
#include <cuda_runtime.h>

#define N_NODES 50000
#define N_EDGES 800000
#define DIM 128
#define KPI 0.62831853071795865f
#define FULL 0xffffffffu

// ---- scratch ----
__device__ float g_P[(size_t)N_NODES * 1024];   // [n][h][128], pre-scaled by 0.25
__device__ float g_c[N_NODES * 8];              // (q.b_K)*0.25
__device__ float g_WKT[DIM * DIM];
__device__ int   g_counts[N_NODES];
__device__ int   g_offsets[N_NODES + 1];
__device__ int   g_cursor[N_NODES];
__device__ int2  g_pe[N_EDGES];                 // (edge, phi bits) CSR order

// ---- CSR build ----
__global__ void k_zero() {
    int i = blockIdx.x * blockDim.x + threadIdx.x;
    if (i < N_NODES) g_counts[i] = 0;
}
__global__ void k_hist(const int* __restrict__ ei) {
    int e = blockIdx.x * blockDim.x + threadIdx.x;
    if (e < N_EDGES) atomicAdd(&g_counts[ei[N_EDGES + e]], 1);
}
__global__ void k_scan() {
    __shared__ int wsum[32];
    int t = threadIdx.x, lane = t & 31, wid = t >> 5;
    int carry = 0;
    for (int base = 0; base < N_NODES; base += 1024) {
        int i = base + t;
        int v = (i < N_NODES) ? g_counts[i] : 0;
        int x = v;
        #pragma unroll
        for (int o = 1; o < 32; o <<= 1) { int y = __shfl_up_sync(FULL, x, o); if (lane >= o) x += y; }
        if (lane == 31) wsum[wid] = x;
        __syncthreads();
        if (wid == 0) {
            int s = wsum[lane];
            #pragma unroll
            for (int o = 1; o < 32; o <<= 1) { int y = __shfl_up_sync(FULL, s, o); if (lane >= o) s += y; }
            wsum[lane] = s;
        }
        __syncthreads();
        int excl = x - v + (wid ? wsum[wid - 1] : 0);
        if (i < N_NODES) { g_offsets[i] = carry + excl; g_cursor[i] = carry + excl; }
        carry += wsum[31];
        __syncthreads();
    }
    if (t == 0) g_offsets[N_NODES] = carry;
}
__global__ void k_scatter(const int* __restrict__ ei, const float* __restrict__ elen) {
    int e = blockIdx.x * blockDim.x + threadIdx.x;
    if (e < N_EDGES) {
        int j = ei[N_EDGES + e];
        int pos = atomicAdd(&g_cursor[j], 1);
        float phi = fmaf(0.5f, __cosf(elen[e] * KPI), 0.5f);
        g_pe[pos] = make_int2(e, __float_as_int(phi));
    }
}
__global__ void k_wkt(const float* __restrict__ WK) {
    int i = blockIdx.x * blockDim.x + threadIdx.x;
    if (i < DIM * DIM) g_WKT[(i % DIM) * DIM + (i / DIM)] = WK[i];
}

// ---- node precompute, 4 nodes/block: weights stream once per 4 nodes ----
__global__ void __launch_bounds__(128) k_qp(
    const float* __restrict__ x, const float* __restrict__ WQ,
    const float* __restrict__ bQ, const float* __restrict__ bK)
{
    __shared__ float sx[4][DIM], sq[4][DIM];
    int nb = blockIdx.x * 4, t = threadIdx.x;
    #pragma unroll
    for (int i = 0; i < 4; i++) sx[i][t] = x[(size_t)(nb + i) * DIM + t];
    __syncthreads();
    float q0 = bQ[t], q1 = q0, q2 = q0, q3 = q0;
    #pragma unroll 4
    for (int s = 0; s < DIM; s++) {
        float w = WQ[s * DIM + t];
        q0 = fmaf(sx[0][s], w, q0);
        q1 = fmaf(sx[1][s], w, q1);
        q2 = fmaf(sx[2][s], w, q2);
        q3 = fmaf(sx[3][s], w, q3);
    }
    sq[0][t] = q0; sq[1][t] = q1; sq[2][t] = q2; sq[3][t] = q3;
    __syncthreads();
    #pragma unroll
    for (int h = 0; h < 8; h++) {
        float p0 = 0.f, p1 = 0.f, p2 = 0.f, p3 = 0.f;
        #pragma unroll
        for (int k = 0; k < 16; k++) {
            float w = g_WKT[(h * 16 + k) * DIM + t];
            p0 = fmaf(sq[0][h * 16 + k], w, p0);
            p1 = fmaf(sq[1][h * 16 + k], w, p1);
            p2 = fmaf(sq[2][h * 16 + k], w, p2);
            p3 = fmaf(sq[3][h * 16 + k], w, p3);
        }
        g_P[(size_t)(nb + 0) * 1024 + h * DIM + t] = 0.25f * p0;
        g_P[(size_t)(nb + 1) * 1024 + h * DIM + t] = 0.25f * p1;
        g_P[(size_t)(nb + 2) * 1024 + h * DIM + t] = 0.25f * p2;
        g_P[(size_t)(nb + 3) * 1024 + h * DIM + t] = 0.25f * p3;
    }
    if (t < 32) {
        int i = t >> 3, h = t & 7;
        float cc = 0.f;
        #pragma unroll
        for (int k = 0; k < 16; k++) cc = fmaf(sq[i][h * 16 + k], bK[h * 16 + k], cc);
        g_c[(nb + i) * 8 + h] = cc * 0.25f;
    }
}

// ---- fused edge pass: 2 warps per node (head-split), 4 nodes/block ----
__global__ void __launch_bounds__(256, 3) k_edge(
    const float4* __restrict__ ea4,
    const float* __restrict__ WV, const float* __restrict__ bV,
    const float* __restrict__ WO, const float* __restrict__ bO,
    float* __restrict__ out)
{
    __shared__ float sU[4][8][DIM];   // [node][head][dim], normalized
    __shared__ float sT[4][8];        // [node][head] = sum(alpha*phi)/sum(exp)
    __shared__ float sno[4][DIM];     // node_out
    int tid = threadIdx.x, w = tid >> 5, l = tid & 31;
    int nl = w >> 1, half = w & 1;    // node slot 0..3, head-half 0/1
    int n = blockIdx.x * 4 + nl;
    int hbase = half * 4;

    // this warp's 4 heads: lane l holds dims 4l..4l+3 (pre-scaled 0.25)
    float4 P4[4];
    #pragma unroll
    for (int h = 0; h < 4; h++)
        P4[h] = reinterpret_cast<const float4*>(g_P + (size_t)n * 1024 + (hbase + h) * DIM)[l];
    float ch = g_c[n * 8 + hbase + (l >> 3)];

    float4 U[4];
    #pragma unroll
    for (int h = 0; h < 4; h++) U[h] = make_float4(0.f, 0.f, 0.f, 0.f);
    float ssum = 0.f, tsum = 0.f;
    bool b4 = (l & 16), b3 = (l & 8);

    int beg = g_offsets[n], end = g_offsets[n + 1];
    int2 pe0 = make_int2(0, 0), pe1 = pe0;
    float4 a0 = make_float4(0.f, 0.f, 0.f, 0.f), a1 = a0;
    if (beg < end)     { pe0 = g_pe[beg];     a0 = ea4[(size_t)pe0.x * 32 + l]; }
    if (beg + 1 < end) { pe1 = g_pe[beg + 1]; a1 = ea4[(size_t)pe1.x * 32 + l]; }

    for (int i = beg; i < end; i++) {
        float4 ac = a0; float phi = __int_as_float(pe0.y);
        pe0 = pe1; a0 = a1;
        if (i + 2 < end) { pe1 = g_pe[i + 2]; a1 = ea4[(size_t)pe1.x * 32 + l]; }

        // partial dots for this warp's 4 heads over lane's 4 dims
        float p0c = fmaf(ac.x, P4[0].x, fmaf(ac.y, P4[0].y, fmaf(ac.z, P4[0].z, ac.w * P4[0].w)));
        float p1c = fmaf(ac.x, P4[1].x, fmaf(ac.y, P4[1].y, fmaf(ac.z, P4[1].z, ac.w * P4[1].w)));
        float p2c = fmaf(ac.x, P4[2].x, fmaf(ac.y, P4[2].y, fmaf(ac.z, P4[2].z, ac.w * P4[2].w)));
        float p3c = fmaf(ac.x, P4[3].x, fmaf(ac.y, P4[3].y, fmaf(ac.z, P4[3].z, ac.w * P4[3].w)));

        // 4-head halving butterfly: lane ends with full score of head (l>>3)
        float t0 = b4 ? p0c : p2c, t1 = b4 ? p1c : p3c;
        float r0 = (b4 ? p2c : p0c) + __shfl_xor_sync(FULL, t0, 16);
        float r1 = (b4 ? p3c : p1c) + __shfl_xor_sync(FULL, t1, 16);
        float t2 = b3 ? r0 : r1;
        float s  = (b3 ? r1 : r0) + __shfl_xor_sync(FULL, t2, 8);
        s += __shfl_xor_sync(FULL, s, 4);
        s += __shfl_xor_sync(FULL, s, 2);
        s += __shfl_xor_sync(FULL, s, 1);

        float ex = __expf(s + ch);   // P, ch pre-scaled by 1/sqrt(d_k)
        float wh = ex * phi;
        ssum += ex; tsum += wh;

        // broadcast per-head weights (head h lives on lanes 8h..8h+7)
        #pragma unroll
        for (int h = 0; h < 4; h++) {
            float whh = __shfl_sync(FULL, wh, 8 * h);
            U[h].x = fmaf(whh, ac.x, U[h].x);
            U[h].y = fmaf(whh, ac.y, U[h].y);
            U[h].z = fmaf(whh, ac.z, U[h].z);
            U[h].w = fmaf(whh, ac.w, U[h].w);
        }
    }

    // normalize + stage (lane's ssum is for head hbase + (l>>3))
    float invm = (ssum > 0.f) ? (1.f / ssum) : 0.f;
    if ((l & 7) == 0) sT[nl][hbase + (l >> 3)] = tsum * invm;
    #pragma unroll
    for (int h = 0; h < 4; h++) {
        float ivh = __shfl_sync(FULL, invm, 8 * h);
        float4 v = make_float4(U[h].x * ivh, U[h].y * ivh, U[h].z * ivh, U[h].w * ivh);
        reinterpret_cast<float4*>(&sU[nl][hbase + h][0])[l] = v;
    }
    __syncthreads();

    // GEMM1: node_out[n,c] = sum_d Unorm[n,h(c),d]*WV[d,c] + sT[n,h(c)]*bV[c]
    int c = tid & 127, g = tid >> 7, h = c >> 4;
    int n0 = 2 * g, n1 = n0 + 1;
    {
        float bv = bV[c];
        float a0c = sT[n0][h] * bv, a1c = sT[n1][h] * bv;
        const float4* u0 = reinterpret_cast<const float4*>(&sU[n0][h][0]);
        const float4* u1 = reinterpret_cast<const float4*>(&sU[n1][h][0]);
        #pragma unroll 8
        for (int d4 = 0; d4 < 32; d4++) {
            float w0 = WV[(4 * d4 + 0) * DIM + c];
            float w1 = WV[(4 * d4 + 1) * DIM + c];
            float w2 = WV[(4 * d4 + 2) * DIM + c];
            float w3 = WV[(4 * d4 + 3) * DIM + c];
            float4 v;
            v = u0[d4]; a0c = fmaf(v.x, w0, fmaf(v.y, w1, fmaf(v.z, w2, fmaf(v.w, w3, a0c))));
            v = u1[d4]; a1c = fmaf(v.x, w0, fmaf(v.y, w1, fmaf(v.z, w2, fmaf(v.w, w3, a1c))));
        }
        sno[n0][c] = a0c; sno[n1][c] = a1c;
    }
    __syncthreads();

    // GEMM2: out = node_out @ W_O + b_O
    {
        float bo = bO[c];
        float o0 = bo, o1 = bo;
        const float4* v0 = reinterpret_cast<const float4*>(&sno[n0][0]);
        const float4* v1 = reinterpret_cast<const float4*>(&sno[n1][0]);
        #pragma unroll 8
        for (int d4 = 0; d4 < 32; d4++) {
            float w0 = WO[(4 * d4 + 0) * DIM + c];
            float w1 = WO[(4 * d4 + 1) * DIM + c];
            float w2 = WO[(4 * d4 + 2) * DIM + c];
            float w3 = WO[(4 * d4 + 3) * DIM + c];
            float4 v;
            v = v0[d4]; o0 = fmaf(v.x, w0, fmaf(v.y, w1, fmaf(v.z, w2, fmaf(v.w, w3, o0))));
            v = v1[d4]; o1 = fmaf(v.x, w0, fmaf(v.y, w1, fmaf(v.z, w2, fmaf(v.w, w3, o1))));
        }
        size_t base = (size_t)blockIdx.x * 4;
        out[(base + n0) * DIM + c] = o0;
        out[(base + n1) * DIM + c] = o1;
    }
}

extern "C" void kernel_launch(void* const* d_in, const int* in_sizes, int n_in,
                              void* d_out, int out_size) {
    const float* x    = (const float*)d_in[0];
    const int*   ei   = (const int*)  d_in[1];
    const float* ea   = (const float*)d_in[2];
    const float* elen = (const float*)d_in[3];
    const float* WQ   = (const float*)d_in[4];
    const float* bQ   = (const float*)d_in[5];
    const float* WK   = (const float*)d_in[6];
    const float* bK   = (const float*)d_in[7];
    const float* WV   = (const float*)d_in[8];
    const float* bV   = (const float*)d_in[9];
    const float* WO   = (const float*)d_in[10];
    const float* bO   = (const float*)d_in[11];
    float* out = (float*)d_out;

    k_zero<<<(N_NODES + 255) / 256, 256>>>();
    k_hist<<<(N_EDGES + 255) / 256, 256>>>(ei);
    k_scan<<<1, 1024>>>();
    k_scatter<<<(N_EDGES + 255) / 256, 256>>>(ei, elen);
    k_wkt<<<(DIM * DIM + 255) / 256, 256>>>(WK);
    k_qp<<<N_NODES / 4, 128>>>(x, WQ, bQ, bK);
    k_edge<<<N_NODES / 4, 256>>>((const float4*)ea, WV, bV, WO, bO, out);
}

// round 9
// speedup vs baseline: 1.5402x; 1.1798x over previous
#include <cuda_runtime.h>

#define N_NODES 50000
#define N_EDGES 800000
#define DIM 128
#define KPI 0.62831853071795865f
#define FULL 0xffffffffu

// ---- scratch ----
__device__ float g_P[(size_t)N_NODES * 1024];   // [n][h][128], pre-scaled by 0.25
__device__ float g_c[N_NODES * 8];              // (q.b_K)*0.25
__device__ float g_WKT[DIM * DIM];
__device__ int   g_counts[N_NODES];
__device__ int   g_offsets[N_NODES + 1];
__device__ int   g_cursor[N_NODES];
__device__ int2  g_pe[N_EDGES];                 // (edge, phi bits) CSR order

// ---- CSR build ----
__global__ void k_zero() {
    int i = blockIdx.x * blockDim.x + threadIdx.x;
    if (i < N_NODES) g_counts[i] = 0;
}
__global__ void k_hist(const int* __restrict__ ei) {
    int e = blockIdx.x * blockDim.x + threadIdx.x;
    if (e < N_EDGES) atomicAdd(&g_counts[ei[N_EDGES + e]], 1);
}
__global__ void k_scan() {
    __shared__ int wsum[32];
    int t = threadIdx.x, lane = t & 31, wid = t >> 5;
    int carry = 0;
    for (int base = 0; base < N_NODES; base += 1024) {
        int i = base + t;
        int v = (i < N_NODES) ? g_counts[i] : 0;
        int x = v;
        #pragma unroll
        for (int o = 1; o < 32; o <<= 1) { int y = __shfl_up_sync(FULL, x, o); if (lane >= o) x += y; }
        if (lane == 31) wsum[wid] = x;
        __syncthreads();
        if (wid == 0) {
            int s = wsum[lane];
            #pragma unroll
            for (int o = 1; o < 32; o <<= 1) { int y = __shfl_up_sync(FULL, s, o); if (lane >= o) s += y; }
            wsum[lane] = s;
        }
        __syncthreads();
        int excl = x - v + (wid ? wsum[wid - 1] : 0);
        if (i < N_NODES) { g_offsets[i] = carry + excl; g_cursor[i] = carry + excl; }
        carry += wsum[31];
        __syncthreads();
    }
    if (t == 0) g_offsets[N_NODES] = carry;
}
__global__ void k_scatter(const int* __restrict__ ei, const float* __restrict__ elen) {
    int e = blockIdx.x * blockDim.x + threadIdx.x;
    if (e < N_EDGES) {
        int j = ei[N_EDGES + e];
        int pos = atomicAdd(&g_cursor[j], 1);
        float phi = fmaf(0.5f, __cosf(elen[e] * KPI), 0.5f);
        g_pe[pos] = make_int2(e, __float_as_int(phi));
    }
}
__global__ void k_wkt(const float* __restrict__ WK) {
    int i = blockIdx.x * blockDim.x + threadIdx.x;
    if (i < DIM * DIM) g_WKT[(i % DIM) * DIM + (i / DIM)] = WK[i];
}

// ---- node precompute, 4 nodes/block: weights stream once per 4 nodes ----
__global__ void __launch_bounds__(128) k_qp(
    const float* __restrict__ x, const float* __restrict__ WQ,
    const float* __restrict__ bQ, const float* __restrict__ bK)
{
    __shared__ float sx[4][DIM], sq[4][DIM];
    int nb = blockIdx.x * 4, t = threadIdx.x;
    #pragma unroll
    for (int i = 0; i < 4; i++) sx[i][t] = x[(size_t)(nb + i) * DIM + t];
    __syncthreads();
    float q0 = bQ[t], q1 = q0, q2 = q0, q3 = q0;
    #pragma unroll 4
    for (int s = 0; s < DIM; s++) {
        float w = WQ[s * DIM + t];
        q0 = fmaf(sx[0][s], w, q0);
        q1 = fmaf(sx[1][s], w, q1);
        q2 = fmaf(sx[2][s], w, q2);
        q3 = fmaf(sx[3][s], w, q3);
    }
    sq[0][t] = q0; sq[1][t] = q1; sq[2][t] = q2; sq[3][t] = q3;
    __syncthreads();
    #pragma unroll
    for (int h = 0; h < 8; h++) {
        float p0 = 0.f, p1 = 0.f, p2 = 0.f, p3 = 0.f;
        #pragma unroll
        for (int k = 0; k < 16; k++) {
            float w = g_WKT[(h * 16 + k) * DIM + t];
            p0 = fmaf(sq[0][h * 16 + k], w, p0);
            p1 = fmaf(sq[1][h * 16 + k], w, p1);
            p2 = fmaf(sq[2][h * 16 + k], w, p2);
            p3 = fmaf(sq[3][h * 16 + k], w, p3);
        }
        g_P[(size_t)(nb + 0) * 1024 + h * DIM + t] = 0.25f * p0;
        g_P[(size_t)(nb + 1) * 1024 + h * DIM + t] = 0.25f * p1;
        g_P[(size_t)(nb + 2) * 1024 + h * DIM + t] = 0.25f * p2;
        g_P[(size_t)(nb + 3) * 1024 + h * DIM + t] = 0.25f * p3;
    }
    if (t < 32) {
        int i = t >> 3, h = t & 7;
        float cc = 0.f;
        #pragma unroll
        for (int k = 0; k < 16; k++) cc = fmaf(sq[i][h * 16 + k], bK[h * 16 + k], cc);
        g_c[(nb + i) * 8 + h] = cc * 0.25f;
    }
}

// ---- fused edge pass (warp=node, 4 nodes/block) + cooperative epilogue ----
__global__ void __launch_bounds__(128, 5) k_edge(
    const float4* __restrict__ ea4,
    const float* __restrict__ WV, const float* __restrict__ bV,
    const float* __restrict__ WO, const float* __restrict__ bO,
    float* __restrict__ out)
{
    __shared__ float sU[4][8][DIM];   // [node][head][dim], normalized
    __shared__ float sT[4][8];        // [node][head] = sum(alpha*phi)/sum(exp)
    __shared__ float sno[4][DIM];     // node_out
    int tid = threadIdx.x, w = tid >> 5, l = tid & 31;
    int n = blockIdx.x * 4 + w;

    // P: lane l holds dims 4l..4l+3 of all 8 heads (pre-scaled 0.25)
    float4 P4[8];
    #pragma unroll
    for (int h = 0; h < 8; h++)
        P4[h] = reinterpret_cast<const float4*>(g_P + (size_t)n * 1024 + h * DIM)[l];
    float ch = g_c[n * 8 + (l >> 2)];

    float4 U[8];
    #pragma unroll
    for (int h = 0; h < 8; h++) U[h] = make_float4(0.f, 0.f, 0.f, 0.f);
    float ssum = 0.f, tsum = 0.f;
    bool b4 = (l & 16), b3 = (l & 8), b2 = (l & 4);

    int beg = g_offsets[n], end = g_offsets[n + 1];
    // depth-3 software pipeline on the edge stream (evict-first loads: rows read once)
    int2 pe0 = make_int2(0, 0), pe1 = pe0, pe2 = pe0;
    float4 a0 = make_float4(0.f, 0.f, 0.f, 0.f), a1 = a0, a2 = a0;
    if (beg < end)     { pe0 = g_pe[beg];     a0 = __ldcs(&ea4[(size_t)pe0.x * 32 + l]); }
    if (beg + 1 < end) { pe1 = g_pe[beg + 1]; a1 = __ldcs(&ea4[(size_t)pe1.x * 32 + l]); }
    if (beg + 2 < end) { pe2 = g_pe[beg + 2]; a2 = __ldcs(&ea4[(size_t)pe2.x * 32 + l]); }

    for (int i = beg; i < end; i++) {
        float4 ac = a0; float phi = __int_as_float(pe0.y);
        pe0 = pe1; a0 = a1;
        pe1 = pe2; a1 = a2;
        if (i + 3 < end) { pe2 = g_pe[i + 3]; a2 = __ldcs(&ea4[(size_t)pe2.x * 32 + l]); }

        // partial dots: p[h] over this lane's 4 dims
        float p[8];
        #pragma unroll
        for (int h = 0; h < 8; h++)
            p[h] = fmaf(ac.x, P4[h].x, fmaf(ac.y, P4[h].y, fmaf(ac.z, P4[h].z, ac.w * P4[h].w)));

        // head-halving butterfly: lane ends with full score of head (l>>2)
        float r0, r1, r2, r3;
        {
            float t0 = b4 ? p[0] : p[4], t1 = b4 ? p[1] : p[5];
            float t2 = b4 ? p[2] : p[6], t3 = b4 ? p[3] : p[7];
            r0 = (b4 ? p[4] : p[0]) + __shfl_xor_sync(FULL, t0, 16);
            r1 = (b4 ? p[5] : p[1]) + __shfl_xor_sync(FULL, t1, 16);
            r2 = (b4 ? p[6] : p[2]) + __shfl_xor_sync(FULL, t2, 16);
            r3 = (b4 ? p[7] : p[3]) + __shfl_xor_sync(FULL, t3, 16);
        }
        float s0, s1;
        {
            float t0 = b3 ? r0 : r2, t1 = b3 ? r1 : r3;
            s0 = (b3 ? r2 : r0) + __shfl_xor_sync(FULL, t0, 8);
            s1 = (b3 ? r3 : r1) + __shfl_xor_sync(FULL, t1, 8);
        }
        float s;
        {
            float t0 = b2 ? s0 : s1;
            s = (b2 ? s1 : s0) + __shfl_xor_sync(FULL, t0, 4);
        }
        s += __shfl_xor_sync(FULL, s, 2);
        s += __shfl_xor_sync(FULL, s, 1);

        float ex = __expf(s + ch);   // P, ch pre-scaled by 1/sqrt(d_k)
        float wh = ex * phi;
        ssum += ex; tsum += wh;

        // broadcast per-head weights, accumulate U
        #pragma unroll
        for (int h = 0; h < 8; h++) {
            float whh = __shfl_sync(FULL, wh, 4 * h);
            U[h].x = fmaf(whh, ac.x, U[h].x);
            U[h].y = fmaf(whh, ac.y, U[h].y);
            U[h].z = fmaf(whh, ac.z, U[h].z);
            U[h].w = fmaf(whh, ac.w, U[h].w);
        }
    }

    // normalize + stage (lane's ssum is for head l>>2)
    float invm = (ssum > 0.f) ? (1.f / ssum) : 0.f;
    if ((l & 3) == 0) sT[w][l >> 2] = tsum * invm;
    #pragma unroll
    for (int h = 0; h < 8; h++) {
        float ivh = __shfl_sync(FULL, invm, 4 * h);
        float4 v = make_float4(U[h].x * ivh, U[h].y * ivh, U[h].z * ivh, U[h].w * ivh);
        reinterpret_cast<float4*>(&sU[w][h][0])[l] = v;
    }
    __syncthreads();

    // GEMM1: node_out[n,c] = sum_d Unorm[n,h(c),d]*WV[d,c] + sT[n,h(c)]*bV[c]
    // 128 threads: thread = column c, serves all 4 nodes (weight stream amortized x4)
    int c = tid, h = c >> 4;
    {
        float bv = bV[c];
        float a0c = sT[0][h] * bv, a1c = sT[1][h] * bv;
        float a2c = sT[2][h] * bv, a3c = sT[3][h] * bv;
        const float4* u0 = reinterpret_cast<const float4*>(&sU[0][h][0]);
        const float4* u1 = reinterpret_cast<const float4*>(&sU[1][h][0]);
        const float4* u2 = reinterpret_cast<const float4*>(&sU[2][h][0]);
        const float4* u3 = reinterpret_cast<const float4*>(&sU[3][h][0]);
        #pragma unroll 8
        for (int d4 = 0; d4 < 32; d4++) {
            float w0 = WV[(4 * d4 + 0) * DIM + c];
            float w1 = WV[(4 * d4 + 1) * DIM + c];
            float w2 = WV[(4 * d4 + 2) * DIM + c];
            float w3 = WV[(4 * d4 + 3) * DIM + c];
            float4 v;
            v = u0[d4]; a0c = fmaf(v.x, w0, fmaf(v.y, w1, fmaf(v.z, w2, fmaf(v.w, w3, a0c))));
            v = u1[d4]; a1c = fmaf(v.x, w0, fmaf(v.y, w1, fmaf(v.z, w2, fmaf(v.w, w3, a1c))));
            v = u2[d4]; a2c = fmaf(v.x, w0, fmaf(v.y, w1, fmaf(v.z, w2, fmaf(v.w, w3, a2c))));
            v = u3[d4]; a3c = fmaf(v.x, w0, fmaf(v.y, w1, fmaf(v.z, w2, fmaf(v.w, w3, a3c))));
        }
        sno[0][c] = a0c; sno[1][c] = a1c; sno[2][c] = a2c; sno[3][c] = a3c;
    }
    __syncthreads();

    // GEMM2: out = node_out @ W_O + b_O
    {
        float bo = bO[c];
        float o0 = bo, o1 = bo, o2 = bo, o3 = bo;
        const float4* v0 = reinterpret_cast<const float4*>(&sno[0][0]);
        const float4* v1 = reinterpret_cast<const float4*>(&sno[1][0]);
        const float4* v2 = reinterpret_cast<const float4*>(&sno[2][0]);
        const float4* v3 = reinterpret_cast<const float4*>(&sno[3][0]);
        #pragma unroll 8
        for (int d4 = 0; d4 < 32; d4++) {
            float w0 = WO[(4 * d4 + 0) * DIM + c];
            float w1 = WO[(4 * d4 + 1) * DIM + c];
            float w2 = WO[(4 * d4 + 2) * DIM + c];
            float w3 = WO[(4 * d4 + 3) * DIM + c];
            float4 v;
            v = v0[d4]; o0 = fmaf(v.x, w0, fmaf(v.y, w1, fmaf(v.z, w2, fmaf(v.w, w3, o0))));
            v = v1[d4]; o1 = fmaf(v.x, w0, fmaf(v.y, w1, fmaf(v.z, w2, fmaf(v.w, w3, o1))));
            v = v2[d4]; o2 = fmaf(v.x, w0, fmaf(v.y, w1, fmaf(v.z, w2, fmaf(v.w, w3, o2))));
            v = v3[d4]; o3 = fmaf(v.x, w0, fmaf(v.y, w1, fmaf(v.z, w2, fmaf(v.w, w3, o3))));
        }
        size_t base = (size_t)blockIdx.x * 4;
        out[(base + 0) * DIM + c] = o0;
        out[(base + 1) * DIM + c] = o1;
        out[(base + 2) * DIM + c] = o2;
        out[(base + 3) * DIM + c] = o3;
    }
}

extern "C" void kernel_launch(void* const* d_in, const int* in_sizes, int n_in,
                              void* d_out, int out_size) {
    const float* x    = (const float*)d_in[0];
    const int*   ei   = (const int*)  d_in[1];
    const float* ea   = (const float*)d_in[2];
    const float* elen = (const float*)d_in[3];
    const float* WQ   = (const float*)d_in[4];
    const float* bQ   = (const float*)d_in[5];
    const float* WK   = (const float*)d_in[6];
    const float* bK   = (const float*)d_in[7];
    const float* WV   = (const float*)d_in[8];
    const float* bV   = (const float*)d_in[9];
    const float* WO   = (const float*)d_in[10];
    const float* bO   = (const float*)d_in[11];
    float* out = (float*)d_out;

    k_zero<<<(N_NODES + 255) / 256, 256>>>();
    k_hist<<<(N_EDGES + 255) / 256, 256>>>(ei);
    k_scan<<<1, 1024>>>();
    k_scatter<<<(N_EDGES + 255) / 256, 256>>>(ei, elen);
    k_wkt<<<(DIM * DIM + 255) / 256, 256>>>(WK);
    k_qp<<<N_NODES / 4, 128>>>(x, WQ, bQ, bK);
    k_edge<<<N_NODES / 4, 128>>>((const float4*)ea, WV, bV, WO, bO, out);
}